// round 13
// baseline (speedup 1.0000x reference)
#include <cuda_runtime.h>
#include <cuda_fp16.h>
#include <math.h>
#include <stdint.h>

#define B_ 16
#define A_ 256
#define NN 64
#define G_ 64
#define F_ 128
#define ROWS_TOTAL (B_*A_)   // 4096

// static device scratch (allocation-free)
__device__ float g_y[ROWS_TOTAL * F_];     // in2f output
// fragment-order fp16 weight images: word idx = ((ks*4 + wn)*32 + lane)*16 + nt*4 + sel
// sel: 0 = hi_b0, 1 = hi_b1, 2 = lo_b0, 3 = lo_b1
__device__ __align__(16) uint32_t g_w1f[4 * 4 * 32 * 16];   // 8192 words
__device__ __align__(16) uint32_t g_w2f[8 * 4 * 32 * 16];   // 16384 words

__device__ __forceinline__ float sspf(float x) {
    float ax = fabsf(x);
    return fmaxf(x, 0.0f) + __logf(1.0f + __expf(-ax)) - 0.6931471805599453f;
}

// split a pair of fp32 into packed fp16x2 hi and lo words (w = hi + lo, ~22 bits)
__device__ __forceinline__ void split2h(float x, float y, uint32_t& hi, uint32_t& lo) {
    __half hx = __float2half_rn(x);
    __half hy = __float2half_rn(y);
    float rx = x - __half2float(hx);
    float ry = y - __half2float(hy);
    __half lx = __float2half_rn(rx);
    __half ly = __float2half_rn(ry);
    hi = (uint32_t)__half_as_ushort(hx) | ((uint32_t)__half_as_ushort(hy) << 16);
    lo = (uint32_t)__half_as_ushort(lx) | ((uint32_t)__half_as_ushort(ly) << 16);
}

__device__ __forceinline__ uint32_t pack2h(float x, float y) {
    __half2 h = __floats2half2_rn(x, y);
    return *(uint32_t*)&h;
}

__device__ __forceinline__ uint32_t smem_u32(const void* p) {
    uint32_t a;
    asm("{ .reg .u64 t; cvta.to.shared.u64 t, %1; cvt.u32.u64 %0, t; }"
        : "=r"(a) : "l"(p));
    return a;
}

// m16n8k16 fp16 MMA, fp32 accumulate
__device__ __forceinline__ void mma_f16(float c[4], const uint32_t a[4], const uint32_t b[2]) {
    asm volatile("mma.sync.aligned.m16n8k16.row.col.f32.f16.f16.f32 "
        "{%0,%1,%2,%3}, {%4,%5,%6,%7}, {%8,%9}, {%0,%1,%2,%3};"
        : "+f"(c[0]), "+f"(c[1]), "+f"(c[2]), "+f"(c[3])
        : "r"(a[0]), "r"(a[1]), "r"(a[2]), "r"(a[3]), "r"(b[0]), "r"(b[1]));
}

#define LDSM4(r0, r1, r2, r3, addr) \
    asm volatile("ldmatrix.sync.aligned.m8n8.x4.shared.b16 {%0,%1,%2,%3}, [%4];" \
        : "=r"(r0), "=r"(r1), "=r"(r2), "=r"(r3) : "r"(addr))
#define LDSM2(r0, r1, addr) \
    asm volatile("ldmatrix.sync.aligned.m8n8.x2.shared.b16 {%0,%1}, [%2];" \
        : "=r"(r0), "=r"(r1) : "r"(addr))

// ---------------------------------------------------------------------------
// Combined prologue kernel:
//   blocks [0,96): build fragment-order hi/lo fp16 weight images
//   blocks [96,96+1024): in2f  y = x @ w_in2f  (4 rows per block, 2-way k-split)
// ---------------------------------------------------------------------------
__global__ void prep_kernel(const float* __restrict__ fw1,
                            const float* __restrict__ fw2,
                            const float* __restrict__ x,
                            const float* __restrict__ w_in2f) {
    __shared__ float sX[512 + 512];
    const int bid = blockIdx.x;
    const int tid = threadIdx.x;
    if (bid < 96) {
        int t = bid * 256 + tid;       // 0..24575
        const float* fw;
        uint32_t* dst;
        int u;
        if (t < 8192) { fw = fw1; dst = g_w1f; u = t; }
        else          { fw = fw2; dst = g_w2f; u = t - 8192; }
        int j    = u & 15;
        int lane = (u >> 4) & 31;
        int wn   = (u >> 9) & 3;
        int ks   = u >> 11;
        int n  = wn * 32 + (j >> 2) * 8 + (lane >> 2);
        int kw = ks * 8 + (lane & 3) + ((j & 1) ? 4 : 0);
        float xv = fw[(2 * kw) * F_ + n];
        float yv = fw[(2 * kw + 1) * F_ + n];
        uint32_t hi, lo;
        split2h(xv, yv, hi, lo);
        dst[u] = (j & 2) ? lo : hi;
    } else {
        const int blk = bid - 96;       // 0..1023, rows blk*4..blk*4+3
        float* sXd = sX;
        float* sP  = sX + 512;
        if (tid < 128)
            ((float4*)sXd)[tid] = ((const float4*)(x + (size_t)blk * 512))[tid];
        __syncthreads();
        const int kg = tid >> 7, col = tid & 127;
        float a[4] = {0.f, 0.f, 0.f, 0.f};
        const float* wp = w_in2f + (size_t)kg * 64 * F_ + col;
        const float* xb = sXd + kg * 64;
#pragma unroll 8
        for (int k = 0; k < 64; k++) {
            float wv = wp[(size_t)k * F_];
#pragma unroll
            for (int r = 0; r < 4; r++) a[r] += xb[r * 128 + k] * wv;
        }
        if (kg == 1) {
#pragma unroll
            for (int r = 0; r < 4; r++) sP[r * 128 + col] = a[r];
        }
        __syncthreads();
        if (kg == 0) {
#pragma unroll
            for (int r = 0; r < 4; r++)
                g_y[(size_t)(blk * 4 + r) * F_ + col] = a[r] + sP[r * 128 + col];
        }
    }
}

// ---------------------------------------------------------------------------
// Main fused kernel: 1 atom/CTA (M=64), 32x32 warp tiles, 3 CTAs/SM.
// ---------------------------------------------------------------------------
// smem word offsets
#define AF     0        // [64][36] f_ij fp16x2 words (aliases H_)
#define H_     0        // [64][68] H fp16x2
#define CCYH   4352     // half [64 rows][136 cols] = 4352 words
#define LDH    136      // ccy row stride in halves
#define SB1    8704     // float [128]
#define SB2    8832     // float [128]
#define SCC    8960     // float [64]
#define SAGG   9024     // float [2][128]
#define SFT    9280     // float [128] f2out partial
#define SMEM_WORDS 9408
#define SMEM_BYTES (SMEM_WORDS * 4)   // 37632 B

// 2-MMA GEMM, warp tile 32(M) x 32(N). A (fp16) in smem (row stride LD words),
// W hi/lo from fragment-order global image (NK k16-steps), double-buffered.
template<int LD, int NK>
__device__ __forceinline__ void gemm_frag(
    const uint32_t* Ah, const uint32_t* __restrict__ Bimg,
    int wm, int wn, int lane, float acc[8][4])
{
    const int arow = wm * 32 + (lane & 7) + ((lane >> 3) & 1) * 8;
    const int acol = ((lane >> 4) & 1) * 4;
    uint32_t aH = smem_u32(Ah + arow * LD + acol);
    const uint32_t tstep = 16u * LD * 4u;

    const uint4* bp = (const uint4*)(Bimg) + ((size_t)wn * 32 + lane) * 4;
    uint4 bcur[4], bnxt[4];
#pragma unroll
    for (int j = 0; j < 4; j++) bcur[j] = bp[j];

#pragma unroll
    for (int ks = 0; ks < NK; ks++) {
        if (ks + 1 < NK) {
            const uint4* np = bp + (size_t)(ks + 1) * 512;
#pragma unroll
            for (int j = 0; j < 4; j++) bnxt[j] = np[j];
        }
#pragma unroll
        for (int mt = 0; mt < 2; mt++) {
            uint32_t ah[4];
            LDSM4(ah[0], ah[1], ah[2], ah[3], aH + mt * tstep);
#pragma unroll
            for (int nt = 0; nt < 4; nt++) {
                uint32_t bh[2] = {bcur[nt].x, bcur[nt].y};
                uint32_t bl[2] = {bcur[nt].z, bcur[nt].w};
                mma_f16(acc[mt * 4 + nt], ah, bh);
                mma_f16(acc[mt * 4 + nt], ah, bl);
            }
        }
#pragma unroll
        for (int j = 0; j < 4; j++) bcur[j] = bnxt[j];
        aH += 32;     // advance 8 k-words (32 bytes)
    }
}

__global__ __launch_bounds__(256, 3)
void cfconv_main(const float* __restrict__ r_ij,
                 const float* __restrict__ f_ij,
                 const int*   __restrict__ neighbors,
                 const float* __restrict__ pmask,
                 const float* __restrict__ fb1,
                 const float* __restrict__ fb2,
                 const float* __restrict__ w_f2out,
                 const float* __restrict__ b_f2out,
                 float* __restrict__ out) {
    extern __shared__ uint32_t smw[];
    float* smf = (float*)smw;
    __half* ccyh = (__half*)(smw + CCYH);
    const int cta  = blockIdx.x;        // atom index 0..4095
    const int tid  = threadIdx.x;
    const int lane = tid & 31;
    const int wid  = tid >> 5;
    const int wm   = wid & 1, wn = wid >> 1;   // warp grid 2x4, tiles 32x32

    // ---- cc, biases ----
    if (tid < 64) {
        float r = r_ij[cta * 64 + tid];
        float m = pmask[cta * 64 + tid];
        float c = (r < 5.0f) ? 0.5f * (__cosf(r * 0.6283185307179586f) + 1.0f) * m : 0.0f;
        smf[SCC + tid] = c;
    }
    if (tid < 128) {
        smf[SB1 + tid] = fb1[tid];
        smf[SB2 + tid] = fb2[tid];
    }

    // ---- f_ij -> fp16x2 image [64 rows][kword], ld 36 ----
    {
        const int r = tid >> 2, q = tid & 3;   // 4 threads per row, 16 floats each
        const float4* src = (const float4*)(f_ij + (size_t)cta * 4096 + r * 64 + q * 16);
        uint32_t* dh = smw + AF + r * 36 + q * 8;
#pragma unroll
        for (int j4 = 0; j4 < 2; j4++) {
            float4 v0 = src[2 * j4];
            float4 v1 = src[2 * j4 + 1];
            uint4 w;
            w.x = pack2h(v0.x, v0.y);
            w.y = pack2h(v0.z, v0.w);
            w.z = pack2h(v1.x, v1.y);
            w.w = pack2h(v1.z, v1.w);
            *(uint4*)(dh + 4 * j4) = w;
        }
    }
    __syncthreads();   // SCC, SB1, SB2, AF visible

    // ---- gather: ccyh[n][col] = half(cc[n] * y[nbh[n]][col]), row-major ----
    {
        const int n = tid >> 2, q = tid & 3;   // 4 threads per neighbor row
        const int nb = neighbors[cta * 64 + n];
        const int btch = cta >> 8;
        const float ccn = smf[SCC + n];
        const float4* yr = (const float4*)(g_y + (size_t)(btch * A_ + nb) * F_) + q * 8;
        uint4* dst = (uint4*)(ccyh + (size_t)n * LDH) + q * 4;
#pragma unroll
        for (int j = 0; j < 4; j++) {
            float4 a = yr[2 * j];
            float4 b = yr[2 * j + 1];
            uint4 w;
            w.x = pack2h(a.x * ccn, a.y * ccn);
            w.y = pack2h(a.z * ccn, a.w * ccn);
            w.z = pack2h(b.x * ccn, b.y * ccn);
            w.w = pack2h(b.z * ccn, b.w * ccn);
            dst[j] = w;
        }
    }

    const int g = lane >> 2, t = lane & 3;
    float acc[8][4];

    // ---- GEMM1: H = f_ij @ W1 (+fb1 via init), K=64 ----
#pragma unroll
    for (int mt = 0; mt < 2; mt++)
#pragma unroll
        for (int nt = 0; nt < 4; nt++) {
            int j0 = wn * 32 + nt * 8 + 2 * t;
            acc[mt * 4 + nt][0] = smf[SB1 + j0];
            acc[mt * 4 + nt][1] = smf[SB1 + j0 + 1];
            acc[mt * 4 + nt][2] = smf[SB1 + j0];
            acc[mt * 4 + nt][3] = smf[SB1 + j0 + 1];
        }
    gemm_frag<36, 4>(smw + AF, g_w1f, wm, wn, lane, acc);
    __syncthreads();   // all GEMM1 reads + gather stores done

    // ---- epilogue 1: ssp -> fp16 H image [64][68] (overwrites AF) ----
#pragma unroll
    for (int mt = 0; mt < 2; mt++) {
#pragma unroll
        for (int nt = 0; nt < 4; nt++) {
            int r  = wm * 32 + mt * 16 + g;
            int wc = wn * 16 + nt * 4 + t;
            float s0 = sspf(acc[mt * 4 + nt][0]);
            float s1 = sspf(acc[mt * 4 + nt][1]);
            float s2 = sspf(acc[mt * 4 + nt][2]);
            float s3 = sspf(acc[mt * 4 + nt][3]);
            smw[H_ + r * 68 + wc]       = pack2h(s0, s1);
            smw[H_ + (r + 8) * 68 + wc] = pack2h(s2, s3);
        }
    }
    __syncthreads();   // H visible

    // ---- GEMM2: W = H @ W2 (+fb2 via init), K=128 ----
#pragma unroll
    for (int mt = 0; mt < 2; mt++)
#pragma unroll
        for (int nt = 0; nt < 4; nt++) {
            int j0 = wn * 32 + nt * 8 + 2 * t;
            acc[mt * 4 + nt][0] = smf[SB2 + j0];
            acc[mt * 4 + nt][1] = smf[SB2 + j0 + 1];
            acc[mt * 4 + nt][2] = smf[SB2 + j0];
            acc[mt * 4 + nt][3] = smf[SB2 + j0 + 1];
        }
    gemm_frag<68, 8>(smw + H_, g_w2f, wm, wn, lane, acc);

    // ---- epilogue 2: agg partials = sum_rows W[r][f] * ccy[r][f] via ldmatrix ----
    {
        const uint32_t ccy_base = smem_u32(ccyh) +
            ((uint32_t)(wm * 32 + (lane & 15)) * LDH + (uint32_t)wn * 32) * 2u;
        float part[4][2];
#pragma unroll
        for (int nt = 0; nt < 4; nt++) { part[nt][0] = 0.f; part[nt][1] = 0.f; }
#pragma unroll
        for (int mt = 0; mt < 2; mt++) {
#pragma unroll
            for (int nt = 0; nt < 4; nt++) {
                uint32_t p0, p1;
                LDSM2(p0, p1, ccy_base + (uint32_t)mt * (16u * LDH * 2u) + (uint32_t)nt * 16u);
                float2 f0 = __half22float2(*(__half2*)&p0);
                float2 f1 = __half22float2(*(__half2*)&p1);
                part[nt][0] += acc[mt * 4 + nt][0] * f0.x + acc[mt * 4 + nt][2] * f1.x;
                part[nt][1] += acc[mt * 4 + nt][1] * f0.y + acc[mt * 4 + nt][3] * f1.y;
            }
        }
#pragma unroll
        for (int nt = 0; nt < 4; nt++)
#pragma unroll
            for (int bcol = 0; bcol < 2; bcol++) {
                float v = part[nt][bcol];
                v += __shfl_xor_sync(0xffffffffu, v, 4);
                v += __shfl_xor_sync(0xffffffffu, v, 8);
                v += __shfl_xor_sync(0xffffffffu, v, 16);
                part[nt][bcol] = v;
            }
        if (g == 0) {
#pragma unroll
            for (int nt = 0; nt < 4; nt++) {
                int j0 = wn * 32 + nt * 8 + 2 * t;
                smf[SAGG + wm * 128 + j0]     = part[nt][0];
                smf[SAGG + wm * 128 + j0 + 1] = part[nt][1];
            }
        }
    }
    __syncthreads();

    // ---- fused f2out: out = ssp(agg @ w_f2out + b), k split over 2 thread groups ----
    {
        const int kg = tid >> 7, col = tid & 127;
        const float* ap = smf + SAGG;
        const float* wp = w_f2out + (size_t)kg * 64 * F_ + col;
        float v0 = 0.f, v1 = 0.f;
#pragma unroll 8
        for (int k = 0; k < 32; k++) {
            int k0 = kg * 64 + k, k1 = kg * 64 + k + 32;
            v0 += (ap[k0] + ap[128 + k0]) * wp[(size_t)k * F_];
            v1 += (ap[k1] + ap[128 + k1]) * wp[(size_t)(k + 32) * F_];
        }
        if (kg == 1) smf[SFT + col] = v0 + v1;
        __syncthreads();
        if (kg == 0)
            out[(size_t)cta * F_ + col] = sspf(v0 + v1 + smf[SFT + col] + b_f2out[col]);
    }
}

// ---------------------------------------------------------------------------
extern "C" void kernel_launch(void* const* d_in, const int* in_sizes, int n_in,
                              void* d_out, int out_size) {
    const float* x        = (const float*)d_in[0];
    const float* r_ij     = (const float*)d_in[1];
    const float* f_ij     = (const float*)d_in[2];
    const int*   neighbors= (const int*)  d_in[3];
    const float* pmask    = (const float*)d_in[4];
    const float* fw1      = (const float*)d_in[5];
    const float* fb1      = (const float*)d_in[6];
    const float* fw2      = (const float*)d_in[7];
    const float* fb2      = (const float*)d_in[8];
    const float* w_in2f   = (const float*)d_in[9];
    const float* w_f2out  = (const float*)d_in[10];
    const float* b_f2out  = (const float*)d_in[11];
    float* out = (float*)d_out;

    cudaFuncSetAttribute(cfconv_main,
                         cudaFuncAttributeMaxDynamicSharedMemorySize, SMEM_BYTES);

    prep_kernel<<<96 + 1024, 256>>>(fw1, fw2, x, w_in2f);
    cfconv_main<<<ROWS_TOTAL, 256, SMEM_BYTES>>>(
        r_ij, f_ij, neighbors, pmask, fb1, fb2, w_f2out, b_f2out, out);
}

// round 14
// speedup vs baseline: 1.6557x; 1.6557x over previous
#include <cuda_runtime.h>
#include <cuda_fp16.h>
#include <math.h>
#include <stdint.h>

#define B_ 16
#define A_ 256
#define NN 64
#define G_ 64
#define F_ 128
#define ROWS_TOTAL (B_*A_)   // 4096

// static device scratch (allocation-free)
__device__ float g_y[ROWS_TOTAL * F_];     // in2f output
// fragment-order fp16 weight images (single precision-level):
// word idx = ((ks*4 + wn)*32 + lane)*8 + nt*2 + sel   (sel: 0 = b0, 1 = b1)
__device__ __align__(16) uint32_t g_w1f[4 * 4 * 32 * 8];    // 4096 words
__device__ __align__(16) uint32_t g_w2f[8 * 4 * 32 * 8];    // 8192 words

__device__ __forceinline__ float sspf(float x) {
    float ax = fabsf(x);
    return fmaxf(x, 0.0f) + __logf(1.0f + __expf(-ax)) - 0.6931471805599453f;
}

__device__ __forceinline__ uint32_t pack2h(float x, float y) {
    __half2 h = __floats2half2_rn(x, y);
    return *(uint32_t*)&h;
}

__device__ __forceinline__ uint32_t smem_u32(const void* p) {
    uint32_t a;
    asm("{ .reg .u64 t; cvta.to.shared.u64 t, %1; cvt.u32.u64 %0, t; }"
        : "=r"(a) : "l"(p));
    return a;
}

// m16n8k16 fp16 MMA, fp32 accumulate
__device__ __forceinline__ void mma_f16(float c[4], const uint32_t a[4], const uint32_t b[2]) {
    asm volatile("mma.sync.aligned.m16n8k16.row.col.f32.f16.f16.f32 "
        "{%0,%1,%2,%3}, {%4,%5,%6,%7}, {%8,%9}, {%0,%1,%2,%3};"
        : "+f"(c[0]), "+f"(c[1]), "+f"(c[2]), "+f"(c[3])
        : "r"(a[0]), "r"(a[1]), "r"(a[2]), "r"(a[3]), "r"(b[0]), "r"(b[1]));
}

#define LDSM4(r0, r1, r2, r3, addr) \
    asm volatile("ldmatrix.sync.aligned.m8n8.x4.shared.b16 {%0,%1,%2,%3}, [%4];" \
        : "=r"(r0), "=r"(r1), "=r"(r2), "=r"(r3) : "r"(addr))
#define LDSM2(r0, r1, addr) \
    asm volatile("ldmatrix.sync.aligned.m8n8.x2.shared.b16 {%0,%1}, [%2];" \
        : "=r"(r0), "=r"(r1) : "r"(addr))

// ---------------------------------------------------------------------------
// Combined prologue kernel:
//   blocks [0,48): build fragment-order fp16 weight images
//   blocks [48,48+1024): in2f  y = x @ w_in2f  (4 rows per block, 2-way k-split)
// ---------------------------------------------------------------------------
__global__ void prep_kernel(const float* __restrict__ fw1,
                            const float* __restrict__ fw2,
                            const float* __restrict__ x,
                            const float* __restrict__ w_in2f) {
    __shared__ float sX[512 + 512];
    const int bid = blockIdx.x;
    const int tid = threadIdx.x;
    if (bid < 48) {
        int t = bid * 256 + tid;       // 0..12287
        const float* fw;
        uint32_t* dst;
        int u;
        if (t < 4096) { fw = fw1; dst = g_w1f; u = t; }
        else          { fw = fw2; dst = g_w2f; u = t - 4096; }
        int j    = u & 7;              // nt*2 + sel
        int lane = (u >> 3) & 31;
        int wn   = (u >> 8) & 3;
        int ks   = u >> 10;
        int n  = wn * 32 + (j >> 1) * 8 + (lane >> 2);
        int kw = ks * 8 + (lane & 3) + ((j & 1) ? 4 : 0);
        dst[u] = pack2h(fw[(2 * kw) * F_ + n], fw[(2 * kw + 1) * F_ + n]);
    } else {
        const int blk = bid - 48;       // 0..1023, rows blk*4..blk*4+3
        float* sXd = sX;
        float* sP  = sX + 512;
        if (tid < 128)
            ((float4*)sXd)[tid] = ((const float4*)(x + (size_t)blk * 512))[tid];
        __syncthreads();
        const int kg = tid >> 7, col = tid & 127;
        float a[4] = {0.f, 0.f, 0.f, 0.f};
        const float* wp = w_in2f + (size_t)kg * 64 * F_ + col;
        const float* xb = sXd + kg * 64;
#pragma unroll 8
        for (int k = 0; k < 64; k++) {
            float wv = wp[(size_t)k * F_];
#pragma unroll
            for (int r = 0; r < 4; r++) a[r] += xb[r * 128 + k] * wv;
        }
        if (kg == 1) {
#pragma unroll
            for (int r = 0; r < 4; r++) sP[r * 128 + col] = a[r];
        }
        __syncthreads();
        if (kg == 0) {
#pragma unroll
            for (int r = 0; r < 4; r++)
                g_y[(size_t)(blk * 4 + r) * F_ + col] = a[r] + sP[r * 128 + col];
        }
    }
}

// ---------------------------------------------------------------------------
// Main fused kernel: 2 atoms/CTA (M=128), single-fp16 weights, 1 MMA/fragment.
// ---------------------------------------------------------------------------
// smem word offsets
#define AF     0        // [128][36] f_ij fp16x2 words
#define H_     0        // [128][68] H fp16x2 (aliases AF after GEMM1)
#define CCYH   8704     // half [128 rows][136 cols] = 8704 words
#define LDH    136      // ccy row stride in halves (rows 4 banks apart)
#define SB1    17408    // float [128]
#define SB2    17536    // float [128]
#define SCC    17664    // float [128]
#define SAGG   17792    // float [2][128]
#define SMEM_WORDS 18048
#define SMEM_BYTES (SMEM_WORDS * 4)   // 72192 B -> 2 CTAs/SM

// 1-MMA GEMM, warp tile 64(M) x 32(N). A (fp16) in smem (row stride LD words),
// W (fp16) from fragment-order global image (NK k16-steps), double-buffered.
template<int LD, int NK>
__device__ __forceinline__ void gemm_frag(
    const uint32_t* Ah, const uint32_t* __restrict__ Bimg,
    int wm, int wn, int lane, float acc[16][4])
{
    const int arow = wm * 64 + (lane & 7) + ((lane >> 3) & 1) * 8;
    const int acol = ((lane >> 4) & 1) * 4;
    uint32_t aH = smem_u32(Ah + arow * LD + acol);
    const uint32_t tstep = 16u * LD * 4u;

    // per k-step, per thread: 8 words = 2 uint4 (nt0..nt3, b0/b1 pairs)
    const uint4* bp = (const uint4*)(Bimg) + ((size_t)wn * 32 + lane) * 2;
    uint4 bcur[2], bnxt[2];
    bcur[0] = bp[0]; bcur[1] = bp[1];

#pragma unroll
    for (int ks = 0; ks < NK; ks++) {
        if (ks + 1 < NK) {
            const uint4* np = bp + (size_t)(ks + 1) * 256;
            bnxt[0] = np[0]; bnxt[1] = np[1];
        }
#pragma unroll
        for (int mt = 0; mt < 4; mt++) {
            uint32_t ah[4];
            LDSM4(ah[0], ah[1], ah[2], ah[3], aH + mt * tstep);
            {
                uint32_t b0[2] = {bcur[0].x, bcur[0].y};
                mma_f16(acc[mt * 4 + 0], ah, b0);
                uint32_t b1[2] = {bcur[0].z, bcur[0].w};
                mma_f16(acc[mt * 4 + 1], ah, b1);
                uint32_t b2[2] = {bcur[1].x, bcur[1].y};
                mma_f16(acc[mt * 4 + 2], ah, b2);
                uint32_t b3[2] = {bcur[1].z, bcur[1].w};
                mma_f16(acc[mt * 4 + 3], ah, b3);
            }
        }
        bcur[0] = bnxt[0]; bcur[1] = bnxt[1];
        aH += 32;     // advance 8 k-words (32 bytes)
    }
}

__global__ __launch_bounds__(256, 2)
void cfconv_main(const float* __restrict__ r_ij,
                 const float* __restrict__ f_ij,
                 const int*   __restrict__ neighbors,
                 const float* __restrict__ pmask,
                 const float* __restrict__ fb1,
                 const float* __restrict__ fb2,
                 const float* __restrict__ w_f2out,
                 const float* __restrict__ b_f2out,
                 float* __restrict__ out) {
    extern __shared__ uint32_t smw[];
    float* smf = (float*)smw;
    __half* ccyh = (__half*)(smw + CCYH);
    const int cta  = blockIdx.x;        // atoms 2*cta, 2*cta+1
    const int tid  = threadIdx.x;
    const int lane = tid & 31;
    const int wid  = tid >> 5;
    const int wm   = wid & 1, wn = wid >> 1;   // warp grid 2x4

    // ---- cc, biases ----
    if (tid < 128) {
        float r = r_ij[cta * 128 + tid];
        float m = pmask[cta * 128 + tid];
        float c = (r < 5.0f) ? 0.5f * (__cosf(r * 0.6283185307179586f) + 1.0f) * m : 0.0f;
        smf[SCC + tid] = c;
        smf[SB1 + tid] = fb1[tid];
        smf[SB2 + tid] = fb2[tid];
    }

    // ---- f_ij -> fp16x2 image [row][kword], ld 36; contiguous uint4 stores ----
    {
        const int r = tid >> 1, half = tid & 1;
        const float4* src = (const float4*)(f_ij + (size_t)cta * 8192 + r * 64 + half * 32);
        uint32_t* dh = smw + AF + r * 36 + half * 16;
#pragma unroll
        for (int j4 = 0; j4 < 4; j4++) {
            float4 v0 = src[2 * j4];
            float4 v1 = src[2 * j4 + 1];
            uint4 w;
            w.x = pack2h(v0.x, v0.y);
            w.y = pack2h(v0.z, v0.w);
            w.z = pack2h(v1.x, v1.y);
            w.w = pack2h(v1.z, v1.w);
            *(uint4*)(dh + 4 * j4) = w;
        }
    }
    __syncthreads();   // SCC, SB1, SB2, AF visible

    // ---- gather: ccyh[n][col] = half(cc[n] * y[nbh[n]][col]), row-major ----
    {
        const int n = tid & 127, halfsel = tid >> 7;
        const int nb = neighbors[cta * 128 + n];
        const int btch = cta >> 7;
        const float ccn = smf[SCC + n];
        const float4* yr = (const float4*)(g_y + (size_t)(btch * A_ + nb) * F_ + halfsel * 64);
        uint4* dst = (uint4*)(ccyh + (size_t)n * LDH + halfsel * 64);
#pragma unroll
        for (int q = 0; q < 8; q++) {
            float4 a = yr[2 * q];
            float4 b = yr[2 * q + 1];
            uint4 w;
            w.x = pack2h(a.x * ccn, a.y * ccn);
            w.y = pack2h(a.z * ccn, a.w * ccn);
            w.z = pack2h(b.x * ccn, b.y * ccn);
            w.w = pack2h(b.z * ccn, b.w * ccn);
            dst[q] = w;
        }
    }

    const int g = lane >> 2, t = lane & 3;
    float acc[16][4];

    // ---- GEMM1: H = f_ij @ W1 (+fb1 via init), K=64 ----
#pragma unroll
    for (int mt = 0; mt < 4; mt++)
#pragma unroll
        for (int nt = 0; nt < 4; nt++) {
            int j0 = wn * 32 + nt * 8 + 2 * t;
            acc[mt * 4 + nt][0] = smf[SB1 + j0];
            acc[mt * 4 + nt][1] = smf[SB1 + j0 + 1];
            acc[mt * 4 + nt][2] = smf[SB1 + j0];
            acc[mt * 4 + nt][3] = smf[SB1 + j0 + 1];
        }
    gemm_frag<36, 4>(smw + AF, g_w1f, wm, wn, lane, acc);
    __syncthreads();   // all GEMM1 reads + gather stores done

    // ---- epilogue 1: ssp -> fp16 H image [row][68] (overwrites AF) ----
#pragma unroll
    for (int mt = 0; mt < 4; mt++) {
#pragma unroll
        for (int nt = 0; nt < 4; nt++) {
            int r  = wm * 64 + mt * 16 + g;
            int wc = wn * 16 + nt * 4 + t;
            float s0 = sspf(acc[mt * 4 + nt][0]);
            float s1 = sspf(acc[mt * 4 + nt][1]);
            float s2 = sspf(acc[mt * 4 + nt][2]);
            float s3 = sspf(acc[mt * 4 + nt][3]);
            smw[H_ + r * 68 + wc]       = pack2h(s0, s1);
            smw[H_ + (r + 8) * 68 + wc] = pack2h(s2, s3);
        }
    }
    __syncthreads();   // H visible

    // ---- GEMM2: W = H @ W2 (+fb2 via init), K=128 ----
#pragma unroll
    for (int mt = 0; mt < 4; mt++)
#pragma unroll
        for (int nt = 0; nt < 4; nt++) {
            int j0 = wn * 32 + nt * 8 + 2 * t;
            acc[mt * 4 + nt][0] = smf[SB2 + j0];
            acc[mt * 4 + nt][1] = smf[SB2 + j0 + 1];
            acc[mt * 4 + nt][2] = smf[SB2 + j0];
            acc[mt * 4 + nt][3] = smf[SB2 + j0 + 1];
        }
    gemm_frag<68, 8>(smw + H_, g_w2f, wm, wn, lane, acc);

    // ---- epilogue 2: agg[f] = sum_rows W[r][f] * ccy[r][f] via ldmatrix ----
    {
        const uint32_t ccy_base = smem_u32(ccyh) +
            ((uint32_t)(wm * 64 + (lane & 15)) * LDH + (uint32_t)wn * 32) * 2u;
        float part[4][2];
#pragma unroll
        for (int nt = 0; nt < 4; nt++) { part[nt][0] = 0.f; part[nt][1] = 0.f; }
#pragma unroll
        for (int mt = 0; mt < 4; mt++) {
#pragma unroll
            for (int nt = 0; nt < 4; nt++) {
                uint32_t p0, p1;
                LDSM2(p0, p1, ccy_base + (uint32_t)mt * (16u * LDH * 2u) + (uint32_t)nt * 16u);
                float2 f0 = __half22float2(*(__half2*)&p0);
                float2 f1 = __half22float2(*(__half2*)&p1);
                part[nt][0] += acc[mt * 4 + nt][0] * f0.x + acc[mt * 4 + nt][2] * f1.x;
                part[nt][1] += acc[mt * 4 + nt][1] * f0.y + acc[mt * 4 + nt][3] * f1.y;
            }
        }
#pragma unroll
        for (int nt = 0; nt < 4; nt++)
#pragma unroll
            for (int bcol = 0; bcol < 2; bcol++) {
                float v = part[nt][bcol];
                v += __shfl_xor_sync(0xffffffffu, v, 4);
                v += __shfl_xor_sync(0xffffffffu, v, 8);
                v += __shfl_xor_sync(0xffffffffu, v, 16);
                part[nt][bcol] = v;
            }
        if (g == 0) {
#pragma unroll
            for (int nt = 0; nt < 4; nt++) {
                int j0 = wn * 32 + nt * 8 + 2 * t;
                smf[SAGG + wm * 128 + j0]     = part[nt][0];
                smf[SAGG + wm * 128 + j0 + 1] = part[nt][1];
            }
        }
    }
    __syncthreads();

    // ---- fused f2out: out = ssp(agg @ w_f2out + b_f2out), 2 ILP chains ----
    {
        const int atom = tid >> 7, col = tid & 127;
        float v0 = b_f2out[col], v1 = 0.f;
        const float* wp = w_f2out + col;
        const float* ap = smf + SAGG + atom * 128;
#pragma unroll 16
        for (int k = 0; k < 64; k++) {
            v0 += ap[k]      * wp[(size_t)k * F_];
            v1 += ap[k + 64] * wp[(size_t)(k + 64) * F_];
        }
        out[((size_t)cta * 2 + atom) * F_ + col] = sspf(v0 + v1);
    }
}

// ---------------------------------------------------------------------------
extern "C" void kernel_launch(void* const* d_in, const int* in_sizes, int n_in,
                              void* d_out, int out_size) {
    const float* x        = (const float*)d_in[0];
    const float* r_ij     = (const float*)d_in[1];
    const float* f_ij     = (const float*)d_in[2];
    const int*   neighbors= (const int*)  d_in[3];
    const float* pmask    = (const float*)d_in[4];
    const float* fw1      = (const float*)d_in[5];
    const float* fb1      = (const float*)d_in[6];
    const float* fw2      = (const float*)d_in[7];
    const float* fb2      = (const float*)d_in[8];
    const float* w_in2f   = (const float*)d_in[9];
    const float* w_f2out  = (const float*)d_in[10];
    const float* b_f2out  = (const float*)d_in[11];
    float* out = (float*)d_out;

    cudaFuncSetAttribute(cfconv_main,
                         cudaFuncAttributeMaxDynamicSharedMemorySize, SMEM_BYTES);

    prep_kernel<<<48 + 1024, 256>>>(fw1, fw2, x, w_in2f);
    cfconv_main<<<ROWS_TOTAL / 2, 256, SMEM_BYTES>>>(
        r_ij, f_ij, neighbors, pmask, fb1, fb2, w_f2out, b_f2out, out);
}

// round 17
// speedup vs baseline: 2.0294x; 1.2257x over previous
#include <cuda_runtime.h>
#include <cuda_fp16.h>
#include <cuda_pipeline.h>
#include <math.h>
#include <stdint.h>

#define B_ 16
#define A_ 256
#define NN 64
#define G_ 64
#define F_ 128
#define ROWS_TOTAL (B_*A_)   // 4096

// static device scratch (allocation-free)
__device__ __align__(16) __half g_yh[ROWS_TOTAL * F_];   // in2f output (fp16)
__device__ float g_agg[ROWS_TOTAL * F_];                 // aggregate before f2out
// fragment-order fp16 weight images:
// word idx = ((ks*4 + wn)*32 + lane)*8 + nt*2 + sel   (sel: 0 = b0, 1 = b1)
__device__ __align__(16) uint32_t g_w1f[4 * 4 * 32 * 8];    // 4096 words
__device__ __align__(16) uint32_t g_w2f[8 * 4 * 32 * 8];    // 8192 words

__device__ __forceinline__ float sspf(float x) {
    float ax = fabsf(x);
    return fmaxf(x, 0.0f) + __logf(1.0f + __expf(-ax)) - 0.6931471805599453f;
}

__device__ __forceinline__ uint32_t pack2h(float x, float y) {
    __half2 h = __floats2half2_rn(x, y);
    return *(uint32_t*)&h;
}

__device__ __forceinline__ uint32_t smem_u32(const void* p) {
    uint32_t a;
    asm("{ .reg .u64 t; cvta.to.shared.u64 t, %1; cvt.u32.u64 %0, t; }"
        : "=r"(a) : "l"(p));
    return a;
}

// m16n8k16 fp16 MMA, fp32 accumulate
__device__ __forceinline__ void mma_f16(float c[4], const uint32_t a[4], const uint32_t b[2]) {
    asm volatile("mma.sync.aligned.m16n8k16.row.col.f32.f16.f16.f32 "
        "{%0,%1,%2,%3}, {%4,%5,%6,%7}, {%8,%9}, {%0,%1,%2,%3};"
        : "+f"(c[0]), "+f"(c[1]), "+f"(c[2]), "+f"(c[3])
        : "r"(a[0]), "r"(a[1]), "r"(a[2]), "r"(a[3]), "r"(b[0]), "r"(b[1]));
}

#define LDSM4(r0, r1, r2, r3, addr) \
    asm volatile("ldmatrix.sync.aligned.m8n8.x4.shared.b16 {%0,%1,%2,%3}, [%4];" \
        : "=r"(r0), "=r"(r1), "=r"(r2), "=r"(r3) : "r"(addr))
#define LDSM2(r0, r1, addr) \
    asm volatile("ldmatrix.sync.aligned.m8n8.x2.shared.b16 {%0,%1}, [%2];" \
        : "=r"(r0), "=r"(r1) : "r"(addr))

// ---------------------------------------------------------------------------
// Combined prologue kernel:
//   blocks [0,48): build fragment-order fp16 weight images
//   blocks [48,48+1024): in2f  y = x @ w_in2f -> fp16  (4 rows/block, 2-way k-split)
// ---------------------------------------------------------------------------
__global__ void prep_kernel(const float* __restrict__ fw1,
                            const float* __restrict__ fw2,
                            const float* __restrict__ x,
                            const float* __restrict__ w_in2f) {
    __shared__ float sX[512 + 512];
    const int bid = blockIdx.x;
    const int tid = threadIdx.x;
    if (bid < 48) {
        int t = bid * 256 + tid;       // 0..12287
        const float* fw;
        uint32_t* dst;
        int u;
        if (t < 4096) { fw = fw1; dst = g_w1f; u = t; }
        else          { fw = fw2; dst = g_w2f; u = t - 4096; }
        int j    = u & 7;              // nt*2 + sel
        int lane = (u >> 3) & 31;
        int wn   = (u >> 8) & 3;
        int ks   = u >> 10;
        int n  = wn * 32 + (j >> 1) * 8 + (lane >> 2);
        int kw = ks * 8 + (lane & 3) + ((j & 1) ? 4 : 0);
        dst[u] = pack2h(fw[(2 * kw) * F_ + n], fw[(2 * kw + 1) * F_ + n]);
    } else {
        const int blk = bid - 48;       // 0..1023, rows blk*4..blk*4+3
        float* sXd = sX;
        float* sP  = sX + 512;
        if (tid < 128)
            ((float4*)sXd)[tid] = ((const float4*)(x + (size_t)blk * 512))[tid];
        __syncthreads();
        const int kg = tid >> 7, col = tid & 127;
        float a[4] = {0.f, 0.f, 0.f, 0.f};
        const float* wp = w_in2f + (size_t)kg * 64 * F_ + col;
        const float* xb = sXd + kg * 64;
#pragma unroll 8
        for (int k = 0; k < 64; k++) {
            float wv = wp[(size_t)k * F_];
#pragma unroll
            for (int r = 0; r < 4; r++) a[r] += xb[r * 128 + k] * wv;
        }
        if (kg == 1) {
#pragma unroll
            for (int r = 0; r < 4; r++) sP[r * 128 + col] = a[r];
        }
        __syncthreads();
        if (kg == 0) {
#pragma unroll
            for (int r = 0; r < 4; r++)
                g_yh[(size_t)(blk * 4 + r) * F_ + col] =
                    __float2half(a[r] + sP[r * 128 + col]);
        }
    }
}

// ---------------------------------------------------------------------------
// f2out kernel: out = ssp(g_agg @ w_f2out + b), 64 rows/CTA, 512 threads
// ---------------------------------------------------------------------------
__global__ __launch_bounds__(512, 2)
void f2out_kernel(const float* __restrict__ w_f2out,
                  const float* __restrict__ b_f2out,
                  float* __restrict__ out) {
    __shared__ float sA[64 * 128];
    const int blk = blockIdx.x;     // 64 blocks x 64 rows
    const int tid = threadIdx.x;
    const float4* s0 = (const float4*)(g_agg + (size_t)blk * 64 * F_);
#pragma unroll
    for (int q = 0; q < 4; q++) ((float4*)sA)[q * 512 + tid] = s0[q * 512 + tid];
    __syncthreads();

    const int rg = tid >> 5;        // 0..15 -> rows rg*4..+3
    const int cg = tid & 31;        // cols cg*4..+3
    float acc[4][4];
#pragma unroll
    for (int i = 0; i < 4; i++)
#pragma unroll
        for (int j = 0; j < 4; j++) acc[i][j] = 0.f;

#pragma unroll 8
    for (int k = 0; k < F_; k++) {
        float4 bv = __ldg((const float4*)(w_f2out + k * F_ + cg * 4));
        float aa[4];
#pragma unroll
        for (int i = 0; i < 4; i++) aa[i] = sA[(rg * 4 + i) * F_ + k];
#pragma unroll
        for (int i = 0; i < 4; i++) {
            acc[i][0] += aa[i] * bv.x; acc[i][1] += aa[i] * bv.y;
            acc[i][2] += aa[i] * bv.z; acc[i][3] += aa[i] * bv.w;
        }
    }
    float4 b4 = *(const float4*)(b_f2out + cg * 4);
    float bb[4] = {b4.x, b4.y, b4.z, b4.w};
#pragma unroll
    for (int i = 0; i < 4; i++) {
        int row = blk * 64 + rg * 4 + i;
        float o[4];
#pragma unroll
        for (int j = 0; j < 4; j++) o[j] = sspf(acc[i][j] + bb[j]);
        *(float4*)(out + (size_t)row * F_ + cg * 4) = make_float4(o[0], o[1], o[2], o[3]);
    }
}

// ---------------------------------------------------------------------------
// Main fused kernel: 2 atoms/CTA (M=128), single-fp16 weights, async y gather.
// ---------------------------------------------------------------------------
// smem word offsets
#define AF     0        // [128][36] f_ij fp16x2 words
#define H_     0        // [128][68] H fp16x2 (aliases AF after GEMM1)
#define CCYH   8704     // half [128 rows][136 cols] = 8704 words (pure y tile)
#define LDH    136      // y row stride in halves (272 B, 16B-multiple, conflict-free)
#define SB1    17408    // float [128]
#define SB2    17536    // float [128]
#define SCC    17664    // float [128]
#define SMEM_WORDS 17792
#define SMEM_BYTES (SMEM_WORDS * 4)   // 71168 B -> 2 CTAs/SM

// 1-MMA GEMM, warp tile 64(M) x 32(N). A (fp16) in smem (row stride LD words),
// W (fp16) from fragment-order global image (NK k16-steps), double-buffered.
template<int LD, int NK>
__device__ __forceinline__ void gemm_frag(
    const uint32_t* Ah, const uint32_t* __restrict__ Bimg,
    int wm, int wn, int lane, float acc[16][4])
{
    const int arow = wm * 64 + (lane & 7) + ((lane >> 3) & 1) * 8;
    const int acol = ((lane >> 4) & 1) * 4;
    uint32_t aH = smem_u32(Ah + arow * LD + acol);
    const uint32_t tstep = 16u * LD * 4u;

    const uint4* bp = (const uint4*)(Bimg) + ((size_t)wn * 32 + lane) * 2;
    uint4 bcur[2], bnxt[2];
    bcur[0] = bp[0]; bcur[1] = bp[1];

#pragma unroll
    for (int ks = 0; ks < NK; ks++) {
        if (ks + 1 < NK) {
            const uint4* np = bp + (size_t)(ks + 1) * 256;
            bnxt[0] = np[0]; bnxt[1] = np[1];
        }
#pragma unroll
        for (int mt = 0; mt < 4; mt++) {
            uint32_t ah[4];
            LDSM4(ah[0], ah[1], ah[2], ah[3], aH + mt * tstep);
            {
                uint32_t b0[2] = {bcur[0].x, bcur[0].y};
                mma_f16(acc[mt * 4 + 0], ah, b0);
                uint32_t b1[2] = {bcur[0].z, bcur[0].w};
                mma_f16(acc[mt * 4 + 1], ah, b1);
                uint32_t b2[2] = {bcur[1].x, bcur[1].y};
                mma_f16(acc[mt * 4 + 2], ah, b2);
                uint32_t b3[2] = {bcur[1].z, bcur[1].w};
                mma_f16(acc[mt * 4 + 3], ah, b3);
            }
        }
        bcur[0] = bnxt[0]; bcur[1] = bnxt[1];
        aH += 32;     // advance 8 k-words (32 bytes)
    }
}

__global__ __launch_bounds__(256, 2)
void cfconv_main(const float* __restrict__ r_ij,
                 const float* __restrict__ f_ij,
                 const int*   __restrict__ neighbors,
                 const float* __restrict__ pmask,
                 const float* __restrict__ fb1,
                 const float* __restrict__ fb2) {
    extern __shared__ uint32_t smw[];
    float* smf = (float*)smw;
    __half* ccyh = (__half*)(smw + CCYH);
    const int cta  = blockIdx.x;        // atoms 2*cta, 2*cta+1
    const int tid  = threadIdx.x;
    const int lane = tid & 31;
    const int wid  = tid >> 5;
    const int wm   = wid & 1, wn = wid >> 1;   // warp grid 2x4

    // ---- FIRST: async y gather (pure fp16 copy, overlaps both GEMMs) ----
    {
        const int n = tid >> 1, c = tid & 1;   // 2 threads/row, 128 B each
        const int nb = neighbors[cta * 128 + n];
        const int btch = cta >> 7;
        const char* src = (const char*)(g_yh + ((size_t)(btch * A_ + nb) << 7)) + c * 128;
        __half* dst = ccyh + n * LDH + c * 64;
#pragma unroll
        for (int j = 0; j < 8; j++)
            __pipeline_memcpy_async(dst + j * 8, src + j * 16, 16);
        __pipeline_commit();
    }

    // ---- cc, biases ----
    if (tid < 128) {
        float r = r_ij[cta * 128 + tid];
        float m = pmask[cta * 128 + tid];
        float c = (r < 5.0f) ? 0.5f * (__cosf(r * 0.6283185307179586f) + 1.0f) * m : 0.0f;
        smf[SCC + tid] = c;
        smf[SB1 + tid] = fb1[tid];
        smf[SB2 + tid] = fb2[tid];
    }

    // ---- f_ij -> fp16x2 image [row][kword], ld 36; contiguous uint4 stores ----
    {
        const int r = tid >> 1, half = tid & 1;
        const float4* src = (const float4*)(f_ij + (size_t)cta * 8192 + r * 64 + half * 32);
        uint32_t* dh = smw + AF + r * 36 + half * 16;
#pragma unroll
        for (int j4 = 0; j4 < 4; j4++) {
            float4 v0 = src[2 * j4];
            float4 v1 = src[2 * j4 + 1];
            uint4 w;
            w.x = pack2h(v0.x, v0.y);
            w.y = pack2h(v0.z, v0.w);
            w.z = pack2h(v1.x, v1.y);
            w.w = pack2h(v1.z, v1.w);
            *(uint4*)(dh + 4 * j4) = w;
        }
    }
    __syncthreads();   // SCC, SB1, SB2, AF visible

    const int g = lane >> 2, t = lane & 3;
    float acc[16][4];

    // ---- GEMM1: H = f_ij @ W1 (+fb1 via init), K=64 ----
#pragma unroll
    for (int mt = 0; mt < 4; mt++)
#pragma unroll
        for (int nt = 0; nt < 4; nt++) {
            int j0 = wn * 32 + nt * 8 + 2 * t;
            acc[mt * 4 + nt][0] = smf[SB1 + j0];
            acc[mt * 4 + nt][1] = smf[SB1 + j0 + 1];
            acc[mt * 4 + nt][2] = smf[SB1 + j0];
            acc[mt * 4 + nt][3] = smf[SB1 + j0 + 1];
        }
    gemm_frag<36, 4>(smw + AF, g_w1f, wm, wn, lane, acc);
    __syncthreads();   // all GEMM1 reads done (H aliases AF)

    // ---- epilogue 1: ssp -> fp16 H image [row][68] (overwrites AF) ----
#pragma unroll
    for (int mt = 0; mt < 4; mt++) {
#pragma unroll
        for (int nt = 0; nt < 4; nt++) {
            int r  = wm * 64 + mt * 16 + g;
            int wc = wn * 16 + nt * 4 + t;
            float s0 = sspf(acc[mt * 4 + nt][0]);
            float s1 = sspf(acc[mt * 4 + nt][1]);
            float s2 = sspf(acc[mt * 4 + nt][2]);
            float s3 = sspf(acc[mt * 4 + nt][3]);
            smw[H_ + r * 68 + wc]       = pack2h(s0, s1);
            smw[H_ + (r + 8) * 68 + wc] = pack2h(s2, s3);
        }
    }
    __pipeline_wait_prior(0);   // y tile landed (own thread's copies)
    __syncthreads();            // H + y visible to all

    // ---- GEMM2: W = H @ W2 (+fb2 via init), K=128 ----
#pragma unroll
    for (int mt = 0; mt < 4; mt++)
#pragma unroll
        for (int nt = 0; nt < 4; nt++) {
            int j0 = wn * 32 + nt * 8 + 2 * t;
            acc[mt * 4 + nt][0] = smf[SB2 + j0];
            acc[mt * 4 + nt][1] = smf[SB2 + j0 + 1];
            acc[mt * 4 + nt][2] = smf[SB2 + j0];
            acc[mt * 4 + nt][3] = smf[SB2 + j0 + 1];
        }
    gemm_frag<68, 8>(smw + H_, g_w2f, wm, wn, lane, acc);

    // ---- epilogue 2: agg[f] = sum_r (W[r][f]*cc[r]) * y[r][f] via ldmatrix ----
    {
        const uint32_t ccy_base = smem_u32(ccyh) +
            ((uint32_t)(wm * 64 + (lane & 15)) * LDH + (uint32_t)wn * 32) * 2u;
        float part[4][2];
#pragma unroll
        for (int nt = 0; nt < 4; nt++) { part[nt][0] = 0.f; part[nt][1] = 0.f; }
#pragma unroll
        for (int mt = 0; mt < 4; mt++) {
            const int r0 = wm * 64 + mt * 16 + g;
            const float c0 = smf[SCC + r0];
            const float c1 = smf[SCC + r0 + 8];
#pragma unroll
            for (int nt = 0; nt < 4; nt++) {
                uint32_t p0, p1;
                LDSM2(p0, p1, ccy_base + (uint32_t)mt * (16u * LDH * 2u) + (uint32_t)nt * 16u);
                float2 f0 = __half22float2(*(__half2*)&p0);
                float2 f1 = __half22float2(*(__half2*)&p1);
                part[nt][0] += (acc[mt * 4 + nt][0] * c0) * f0.x
                             + (acc[mt * 4 + nt][2] * c1) * f1.x;
                part[nt][1] += (acc[mt * 4 + nt][1] * c0) * f0.y
                             + (acc[mt * 4 + nt][3] * c1) * f1.y;
            }
        }
#pragma unroll
        for (int nt = 0; nt < 4; nt++)
#pragma unroll
            for (int bcol = 0; bcol < 2; bcol++) {
                float v = part[nt][bcol];
                v += __shfl_xor_sync(0xffffffffu, v, 4);
                v += __shfl_xor_sync(0xffffffffu, v, 8);
                v += __shfl_xor_sync(0xffffffffu, v, 16);
                part[nt][bcol] = v;
            }
        if (g == 0) {
            float* ap = g_agg + ((size_t)cta * 2 + wm) * F_;
#pragma unroll
            for (int nt = 0; nt < 4; nt++) {
                int j0 = wn * 32 + nt * 8 + 2 * t;
                ap[j0]     = part[nt][0];
                ap[j0 + 1] = part[nt][1];
            }
        }
    }
}

// ---------------------------------------------------------------------------
extern "C" void kernel_launch(void* const* d_in, const int* in_sizes, int n_in,
                              void* d_out, int out_size) {
    const float* x        = (const float*)d_in[0];
    const float* r_ij     = (const float*)d_in[1];
    const float* f_ij     = (const float*)d_in[2];
    const int*   neighbors= (const int*)  d_in[3];
    const float* pmask    = (const float*)d_in[4];
    const float* fw1      = (const float*)d_in[5];
    const float* fb1      = (const float*)d_in[6];
    const float* fw2      = (const float*)d_in[7];
    const float* fb2      = (const float*)d_in[8];
    const float* w_in2f   = (const float*)d_in[9];
    const float* w_f2out  = (const float*)d_in[10];
    const float* b_f2out  = (const float*)d_in[11];
    float* out = (float*)d_out;

    cudaFuncSetAttribute(cfconv_main,
                         cudaFuncAttributeMaxDynamicSharedMemorySize, SMEM_BYTES);

    prep_kernel<<<48 + 1024, 256>>>(fw1, fw2, x, w_in2f);
    cfconv_main<<<ROWS_TOTAL / 2, 256, SMEM_BYTES>>>(
        r_ij, f_ij, neighbors, pmask, fb1, fb2);
    f2out_kernel<<<64, 512>>>(w_f2out, b_f2out, out);
}